// round 16
// baseline (speedup 1.0000x reference)
#include <cuda_runtime.h>
#include <math.h>

#define Nn 50000
#define Dd 128
#define Tt 4
#define Ee 150000
#define Hh 8
#define E4  (Tt * Ee)
#define TN  (Tt * Nn)
#define NEG_SLOPE 0.2f
#define EPSF 1e-6f
#define SCAN_NB ((TN + 1023) / 1024)

typedef unsigned long long u64;

// ---------------- scratch (static device globals; no allocation) ----------------
__device__ float g_h[Nn*Dd];
__device__ float g_k[Nn*Dd];
__device__ float g_q[Nn*Dd];
__device__ float g_v[Nn*Dd];
__device__ float g_tmp[Nn*Dd];
__device__ float g_al[TN*Hh];
__device__ float g_ar[TN*Hh];
__device__ float g_xw[(size_t)Tt*Nn*Dd];
__device__ int   g_deg[TN];
__device__ int   g_off[TN];
__device__ int   g_cur[TN];
__device__ int   g_csr[E4];
__device__ int   g_bsum[SCAN_NB];

// ---------------- device helpers ----------------
__device__ __forceinline__ float geluf(float x) {
    return 0.5f * x * (1.0f + erff(x * 0.7071067811865476f));
}
__device__ __forceinline__ const int* pick_ei(int t, const int* e0, const int* e1,
                                              const int* e2, const int* e3) {
    return (t == 0) ? e0 : (t == 1) ? e1 : (t == 2) ? e2 : e3;
}
__device__ __forceinline__ float dot4(float4 a, float4 b) {
    return a.x*b.x + a.y*b.y + a.z*b.z + a.w*b.w;
}
// Blackwell packed fp32 FMA (FFMA2). Bit-exact vs two scalar FFMA .rn.
__device__ __forceinline__ u64 pk2(float x) {
    u64 d; unsigned r = __float_as_uint(x);
    asm("mov.b64 %0, {%1, %1};" : "=l"(d) : "r"(r));
    return d;
}
__device__ __forceinline__ void fma2(u64& c, u64 a, u64 b) {
    asm("fma.rn.f32x2 %0, %1, %2, %3;" : "=l"(c) : "l"(a), "l"(b), "l"(c));
}
__device__ __forceinline__ void upk2(u64 d, float& lo, float& hi) {
    asm("mov.b64 {%0, %1}, %2;" : "=f"(lo), "=f"(hi) : "l"(d));
}

// ---------------- elementwise ----------------
__global__ void zeroint(int* __restrict__ p, int n) {
    int i = blockIdx.x*blockDim.x + threadIdx.x;
    if (i < n) p[i] = 0;
}

// ---------------- CSR build ----------------
__global__ void deg_k(const int* __restrict__ e0, const int* __restrict__ e1,
                      const int* __restrict__ e2, const int* __restrict__ e3,
                      int* __restrict__ deg) {
    int idx = blockIdx.x*blockDim.x + threadIdx.x;
    if (idx >= E4) return;
    int t = idx / Ee, e = idx - t*Ee;
    const int* ei = pick_ei(t, e0, e1, e2, e3);
    atomicAdd(&deg[t*Nn + ei[Ee + e]], 1);
}
__global__ void scan_pre(const int* __restrict__ deg, int* __restrict__ bsum) {
    __shared__ int sh[32];
    int g = blockIdx.x*1024 + threadIdx.x;
    int v = (g < TN) ? deg[g] : 0;
    int lane = threadIdx.x & 31, w = threadIdx.x >> 5;
    #pragma unroll
    for (int o = 16; o > 0; o >>= 1) v += __shfl_xor_sync(~0u, v, o);
    if (lane == 0) sh[w] = v;
    __syncthreads();
    if (w == 0) {
        int s = sh[lane];
        #pragma unroll
        for (int o = 16; o > 0; o >>= 1) s += __shfl_xor_sync(~0u, s, o);
        if (lane == 0) bsum[blockIdx.x] = s;
    }
}
__global__ void scan_mid(int* __restrict__ bsum) {
    __shared__ int ws[8];
    int tid = threadIdx.x;
    int v = (tid < SCAN_NB) ? bsum[tid] : 0;
    int lane = tid & 31, w = tid >> 5;
    int x = v;
    #pragma unroll
    for (int o = 1; o < 32; o <<= 1) { int u = __shfl_up_sync(~0u, x, o); if (lane >= o) x += u; }
    if (lane == 31) ws[w] = x;
    __syncthreads();
    if (w == 0 && lane < 8) {
        int y = ws[lane];
        #pragma unroll
        for (int o = 1; o < 8; o <<= 1) { int u = __shfl_up_sync(0xffu, y, o); if (lane >= o) y += u; }
        ws[lane] = y;
    }
    __syncthreads();
    int excl = x - v + (w > 0 ? ws[w-1] : 0);
    if (tid < SCAN_NB) bsum[tid] = excl;
}
__global__ void scan_post(const int* __restrict__ deg, const int* __restrict__ bsum,
                          int* __restrict__ off, int* __restrict__ cur) {
    __shared__ int ws[32];
    int g = blockIdx.x*1024 + threadIdx.x;
    int v = (g < TN) ? deg[g] : 0;
    int lane = threadIdx.x & 31, w = threadIdx.x >> 5;
    int x = v;
    #pragma unroll
    for (int o = 1; o < 32; o <<= 1) { int u = __shfl_up_sync(~0u, x, o); if (lane >= o) x += u; }
    if (lane == 31) ws[w] = x;
    __syncthreads();
    if (w == 0) {
        int y = ws[lane];
        #pragma unroll
        for (int o = 1; o < 32; o <<= 1) { int u = __shfl_up_sync(~0u, y, o); if (lane >= o) y += u; }
        ws[lane] = y;
    }
    __syncthreads();
    int excl = x - v + (w > 0 ? ws[w-1] : 0) + bsum[blockIdx.x];
    if (g < TN) { off[g] = excl; cur[g] = excl; }
}
__global__ void fill_k(const int* __restrict__ e0, const int* __restrict__ e1,
                       const int* __restrict__ e2, const int* __restrict__ e3,
                       int* __restrict__ cur, int* __restrict__ csr) {
    int idx = blockIdx.x*blockDim.x + threadIdx.x;
    if (idx >= E4) return;
    int t = idx / Ee, e = idx - t*Ee;
    const int* ei = pick_ei(t, e0, e1, e2, e3);
    int src = ei[e], dst = ei[Ee + e];
    int slot = atomicAdd(&cur[t*Nn + dst], 1);
    csr[slot] = src;
}

// ---------------- GEMM core macro (round-14 pipelined version) ------------------
#define GEMM_STAGE_AND_MAC(Aptr, Wptr, Mval)                                        \
    float4 pA0, pA1, pW0, pW1;                                                      \
    {                                                                               \
        int r0 = tid & 127, kq0 = tid >> 7;                                         \
        int gr0 = br + r0;                                                          \
        pA0 = (gr0 < (Mval)) ? *(const float4*)((Aptr) + (size_t)gr0*Dd + kq0*4)    \
                             : make_float4(0,0,0,0);                                \
        pA1 = (gr0 < (Mval)) ? *(const float4*)((Aptr) + (size_t)gr0*Dd + (kq0+2)*4)\
                             : make_float4(0,0,0,0);                                \
        int k0 = tid >> 5, nq0 = tid & 31;                                          \
        pW0 = *(const float4*)((Wptr) + (size_t)k0*Dd + nq0*4);                     \
        pW1 = *(const float4*)((Wptr) + (size_t)(k0 + 8)*Dd + nq0*4);               \
    }                                                                               \
    for (int kc = 0; kc < 8; kc++) {                                                \
        __syncthreads();                                                            \
        {                                                                           \
            int r = tid & 127, kq = tid >> 7;                                       \
            As[kq*4+0][r] = pA0.x; As[kq*4+1][r] = pA0.y;                           \
            As[kq*4+2][r] = pA0.z; As[kq*4+3][r] = pA0.w;                           \
            int kq2 = kq + 2;                                                       \
            As[kq2*4+0][r] = pA1.x; As[kq2*4+1][r] = pA1.y;                         \
            As[kq2*4+2][r] = pA1.z; As[kq2*4+3][r] = pA1.w;                         \
            int k0 = tid >> 5, nq0 = tid & 31;                                      \
            *(float4*)(&Ws[k0][nq0*4]) = pW0;                                       \
            *(float4*)(&Ws[k0 + 8][nq0*4]) = pW1;                                   \
        }                                                                           \
        __syncthreads();                                                            \
        if (kc < 7) {                                                               \
            int kb = (kc + 1) * 16;                                                 \
            int r0 = tid & 127, kq0 = tid >> 7;                                     \
            int gr0 = br + r0;                                                      \
            pA0 = (gr0 < (Mval)) ? *(const float4*)((Aptr) + (size_t)gr0*Dd + kb + kq0*4) \
                                 : make_float4(0,0,0,0);                            \
            pA1 = (gr0 < (Mval)) ? *(const float4*)((Aptr) + (size_t)gr0*Dd + kb + (kq0+2)*4) \
                                 : make_float4(0,0,0,0);                            \
            int k0 = tid >> 5, nq0 = tid & 31;                                      \
            pW0 = *(const float4*)((Wptr) + (size_t)(kb + k0)*Dd + nq0*4);          \
            pW1 = *(const float4*)((Wptr) + (size_t)(kb + k0 + 8)*Dd + nq0*4);      \
        }                                                                           \
        _Pragma("unroll")                                                           \
        for (int k = 0; k < 16; k++) {                                              \
            float4 a0 = *(const float4*)(&As[k][ty*8]);                             \
            float4 a1 = *(const float4*)(&As[k][ty*8+4]);                           \
            const u64* w0 = (const u64*)(&Ws[k][tx*4]);                             \
            const u64* w1 = (const u64*)(&Ws[k][64 + tx*4]);                        \
            u64 bq0 = w0[0], bq1 = w0[1], bq2 = w1[0], bq3 = w1[1];                 \
            float av[8] = {a0.x,a0.y,a0.z,a0.w,a1.x,a1.y,a1.z,a1.w};                \
            _Pragma("unroll")                                                       \
            for (int i = 0; i < 8; i++) {                                           \
                u64 ad = pk2(av[i]);                                                \
                fma2(acc2[i][0], ad, bq0);                                          \
                fma2(acc2[i][1], ad, bq1);                                          \
                fma2(acc2[i][2], ad, bq2);                                          \
                fma2(acc2[i][3], ad, bq3);                                          \
            }                                                                       \
        }                                                                           \
    }

#define GEMM_UNPACK()                                                               \
    float acc[8][8];                                                                \
    _Pragma("unroll")                                                               \
    for (int i = 0; i < 8; i++) {                                                   \
        _Pragma("unroll")                                                           \
        for (int j2 = 0; j2 < 4; j2++)                                              \
            upk2(acc2[i][j2], acc[i][j2*2], acc[i][j2*2+1]);                        \
    }

// ---------------- GAT GEMM: xw_t = A @ W_t (+ al/ar epilogue) -------------------
// If ADD3: A = zL+zH+xe computed on the fly; t==0 blocks also write h.
template <bool ADD3>
__global__ void __launch_bounds__(256, 2)
gemm_ff(const float* __restrict__ A, const float* __restrict__ A1,
        const float* __restrict__ A2, float* __restrict__ hout,
        const float* __restrict__ Wbase, float* __restrict__ Cbase,
        const float* __restrict__ asb, const float* __restrict__ adb,
        float* __restrict__ al, float* __restrict__ ar) {
    __shared__ float As[16][128];
    __shared__ float Ws[16][128];
    const int t = blockIdx.y;
    const float* W = Wbase + (size_t)t*Dd*Dd;
    float* C = Cbase + (size_t)t*Nn*Dd;
    const int br = blockIdx.x * 128;
    const int tid = threadIdx.x;
    const int tx = tid & 15, ty = tid >> 4;

    u64 acc2[8][4];
    #pragma unroll
    for (int i = 0; i < 8; i++)
        #pragma unroll
        for (int j = 0; j < 4; j++) acc2[i][j] = 0ull;

    if (ADD3) {
        for (int kc = 0; kc < 8; kc++) {
            __syncthreads();
            #pragma unroll
            for (int j = 0; j < 2; j++) {
                int idx = tid + j*256;
                int r = idx & 127, kq = idx >> 7;
                int gr = br + r;
                float4 av = make_float4(0,0,0,0);
                if (gr < Nn) {
                    float4 x = *(const float4*)(A  + (size_t)gr*Dd + kc*16 + kq*4);
                    float4 y = *(const float4*)(A1 + (size_t)gr*Dd + kc*16 + kq*4);
                    float4 z = *(const float4*)(A2 + (size_t)gr*Dd + kc*16 + kq*4);
                    av = make_float4(x.x+y.x+z.x, x.y+y.y+z.y, x.z+y.z+z.z, x.w+y.w+z.w);
                    if (t == 0)
                        *(float4*)(hout + (size_t)gr*Dd + kc*16 + kq*4) = av;
                }
                As[kq*4+0][r] = av.x;
                As[kq*4+1][r] = av.y;
                As[kq*4+2][r] = av.z;
                As[kq*4+3][r] = av.w;
            }
            #pragma unroll
            for (int j = 0; j < 2; j++) {
                int idx = tid + j*256;
                int k = idx >> 5, nq = idx & 31;
                *(float4*)(&Ws[k][nq*4]) = *(const float4*)(W + (size_t)(kc*16 + k)*Dd + nq*4);
            }
            __syncthreads();
            #pragma unroll
            for (int k = 0; k < 16; k++) {
                float4 a0 = *(const float4*)(&As[k][ty*8]);
                float4 a1 = *(const float4*)(&As[k][ty*8+4]);
                const u64* w0 = (const u64*)(&Ws[k][tx*4]);
                const u64* w1 = (const u64*)(&Ws[k][64 + tx*4]);
                u64 bq0 = w0[0], bq1 = w0[1], bq2 = w1[0], bq3 = w1[1];
                float av[8] = {a0.x,a0.y,a0.z,a0.w,a1.x,a1.y,a1.z,a1.w};
                #pragma unroll
                for (int i = 0; i < 8; i++) {
                    u64 ad = pk2(av[i]);
                    fma2(acc2[i][0], ad, bq0);
                    fma2(acc2[i][1], ad, bq1);
                    fma2(acc2[i][2], ad, bq2);
                    fma2(acc2[i][3], ad, bq3);
                }
            }
        }
    } else {
        GEMM_STAGE_AND_MAC(A, W, Nn)
    }
    GEMM_UNPACK()

    float4 s0 = *(const float4*)(asb + t*Dd + tx*4);
    float4 s1 = *(const float4*)(asb + t*Dd + 64 + tx*4);
    float4 d0 = *(const float4*)(adb + t*Dd + tx*4);
    float4 d1 = *(const float4*)(adb + t*Dd + 64 + tx*4);
    #pragma unroll
    for (int i = 0; i < 8; i++) {
        int gr = br + ty*8 + i;
        if (gr < Nn) {
            *(float4*)(C + (size_t)gr*Dd + tx*4) =
                make_float4(acc[i][0], acc[i][1], acc[i][2], acc[i][3]);
            *(float4*)(C + (size_t)gr*Dd + 64 + tx*4) =
                make_float4(acc[i][4], acc[i][5], acc[i][6], acc[i][7]);
        }
        float pa0 = acc[i][0]*s0.x + acc[i][1]*s0.y + acc[i][2]*s0.z + acc[i][3]*s0.w;
        float pa1 = acc[i][4]*s1.x + acc[i][5]*s1.y + acc[i][6]*s1.z + acc[i][7]*s1.w;
        float pr0 = acc[i][0]*d0.x + acc[i][1]*d0.y + acc[i][2]*d0.z + acc[i][3]*d0.w;
        float pr1 = acc[i][4]*d1.x + acc[i][5]*d1.y + acc[i][6]*d1.z + acc[i][7]*d1.w;
        pa0 += __shfl_xor_sync(~0u, pa0, 1); pa0 += __shfl_xor_sync(~0u, pa0, 2);
        pa1 += __shfl_xor_sync(~0u, pa1, 1); pa1 += __shfl_xor_sync(~0u, pa1, 2);
        pr0 += __shfl_xor_sync(~0u, pr0, 1); pr0 += __shfl_xor_sync(~0u, pr0, 2);
        pr1 += __shfl_xor_sync(~0u, pr1, 1); pr1 += __shfl_xor_sync(~0u, pr1, 2);
        if (gr < Nn && (tx & 3) == 0) {
            int base = ((t*Nn) + gr)*Hh;
            int hh0 = tx >> 2, hh1 = 4 + (tx >> 2);
            al[base + hh0] = pa0;
            al[base + hh1] = pa1;
            ar[base + hh0] = pr0;
            ar[base + hh1] = pr1;
        }
    }
}

// ---------------- fused k/q/v GEMM ----------------
__global__ void __launch_bounds__(256, 2)
gemm_kqv(const float* __restrict__ A,
         const float* __restrict__ Wk, const float* __restrict__ bk, float* __restrict__ Ck,
         const float* __restrict__ Wq, const float* __restrict__ bq, float* __restrict__ Cq,
         const float* __restrict__ Wv, const float* __restrict__ bv, float* __restrict__ Cv) {
    __shared__ float As[16][128];
    __shared__ float Ws[16][128];
    const int t = blockIdx.y;
    const float* W = (t == 0) ? Wk : (t == 1) ? Wq : Wv;
    const float* bias = (t == 0) ? bk : (t == 1) ? bq : bv;
    float* C = (t == 0) ? Ck : (t == 1) ? Cq : Cv;
    const int br = blockIdx.x * 128;
    const int tid = threadIdx.x;
    const int tx = tid & 15, ty = tid >> 4;

    u64 acc2[8][4];
    #pragma unroll
    for (int i = 0; i < 8; i++)
        #pragma unroll
        for (int j = 0; j < 4; j++) acc2[i][j] = 0ull;

    GEMM_STAGE_AND_MAC(A, W, Nn)
    GEMM_UNPACK()

    float4 bb0 = *(const float4*)(bias + tx*4);
    float4 bb1 = *(const float4*)(bias + 64 + tx*4);
    #pragma unroll
    for (int i = 0; i < 8; i++) {
        int gr = br + ty*8 + i;
        if (gr < Nn) {
            *(float4*)(C + (size_t)gr*Dd + tx*4) =
                make_float4(acc[i][0]+bb0.x, acc[i][1]+bb0.y, acc[i][2]+bb0.z, acc[i][3]+bb0.w);
            *(float4*)(C + (size_t)gr*Dd + 64 + tx*4) =
                make_float4(acc[i][4]+bb1.x, acc[i][5]+bb1.y, acc[i][6]+bb1.z, acc[i][7]+bb1.w);
        }
    }
}

// ---------------- Final GEMM + HGT post fused ----------------------------------
__global__ void __launch_bounds__(256, 2)
gemm_wo_post(const float* __restrict__ A, const float* __restrict__ W,
             const float* __restrict__ bias, const float* __restrict__ h,
             const float* __restrict__ g, const float* __restrict__ skip,
             float* __restrict__ out) {
    __shared__ float As[16][128];
    __shared__ float Ws[16][128];
    const int br = blockIdx.x * 128;
    const int tid = threadIdx.x;
    const int tx = tid & 15, ty = tid >> 4;

    u64 acc2[8][4];
    #pragma unroll
    for (int i = 0; i < 8; i++)
        #pragma unroll
        for (int j = 0; j < 4; j++) acc2[i][j] = 0ull;

    GEMM_STAGE_AND_MAC(A, W, Nn)
    GEMM_UNPACK()

    float beta = 1.f / (1.f + expf(-skip[0]));
    float omb = 1.f - beta;
    float4 bb0 = *(const float4*)(bias + tx*4);
    float4 bb1 = *(const float4*)(bias + 64 + tx*4);
    float4 g0 = *(const float4*)(g + tx*4);
    float4 g1 = *(const float4*)(g + 64 + tx*4);

    #pragma unroll
    for (int i = 0; i < 8; i++) {
        int gr = br + ty*8 + i;
        if (gr >= Nn) continue;
        float4 h0 = *(const float4*)(h + (size_t)gr*Dd + tx*4);
        float4 h1 = *(const float4*)(h + (size_t)gr*Dd + 64 + tx*4);
        float u[8];
        u[0] = beta*(acc[i][0]+bb0.x) + omb*h0.x;
        u[1] = beta*(acc[i][1]+bb0.y) + omb*h0.y;
        u[2] = beta*(acc[i][2]+bb0.z) + omb*h0.z;
        u[3] = beta*(acc[i][3]+bb0.w) + omb*h0.w;
        u[4] = beta*(acc[i][4]+bb1.x) + omb*h1.x;
        u[5] = beta*(acc[i][5]+bb1.y) + omb*h1.y;
        u[6] = beta*(acc[i][6]+bb1.z) + omb*h1.z;
        u[7] = beta*(acc[i][7]+bb1.w) + omb*h1.w;
        float ss = 0.f;
        #pragma unroll
        for (int j = 0; j < 8; j++) ss += u[j]*u[j];
        ss += __shfl_xor_sync(~0u, ss, 1);
        ss += __shfl_xor_sync(~0u, ss, 2);
        ss += __shfl_xor_sync(~0u, ss, 4);
        ss += __shfl_xor_sync(~0u, ss, 8);
        float inv = rsqrtf(ss * (1.0f/Dd) + EPSF);
        float4 r0, r1;
        r0.x = geluf(h0.x + g0.x*u[0]*inv);
        r0.y = geluf(h0.y + g0.y*u[1]*inv);
        r0.z = geluf(h0.z + g0.z*u[2]*inv);
        r0.w = geluf(h0.w + g0.w*u[3]*inv);
        r1.x = geluf(h1.x + g1.x*u[4]*inv);
        r1.y = geluf(h1.y + g1.y*u[5]*inv);
        r1.z = geluf(h1.z + g1.z*u[6]*inv);
        r1.w = geluf(h1.w + g1.w*u[7]*inv);
        *(float4*)(out + (size_t)gr*Dd + tx*4) = r0;
        *(float4*)(out + (size_t)gr*Dd + 64 + tx*4) = r1;
    }
}

// ---------------- GAT gather (round-9 version, unchanged) ----------------
__global__ void gat_gather_b(const int* __restrict__ csr, const int* __restrict__ off,
                             const int* __restrict__ deg, const float* __restrict__ al,
                             const float* __restrict__ ar, const float* __restrict__ xw,
                             const float* __restrict__ b, const float* __restrict__ g,
                             float* __restrict__ h) {
    int n = blockIdx.x;
    int tid = threadIdx.x;
    int t = tid >> 5, lane = tid & 31;
    int hh = lane >> 2;
    __shared__ float smf[4][128];
    __shared__ float sw[4];

    {
        int i = t*Nn + n;
        float arn = ar[(size_t)i*Hh + hh];
        float v = al[(size_t)i*Hh + hh] + arn;    // self loop
        v = v > 0.f ? v : NEG_SLOPE*v;
        float p = expf(v);
        float s = p;
        float4 x = *(const float4*)(xw + (size_t)i*Dd + lane*4);
        float4 f = make_float4(x.x*p, x.y*p, x.z*p, x.w*p);

        const float* alt = al + (size_t)t*Nn*Hh;
        const float* xwt = xw + (size_t)t*Nn*Dd;
        int st = off[i], dg = deg[i];
        for (int j0 = 0; j0 < dg; j0 += 32) {
            int myS = (j0 + lane < dg) ? csr[st + j0 + lane] : 0;
            int cnt = min(32, dg - j0);
            for (int j = 0; j < cnt; j += 4) {
                int s0 = __shfl_sync(~0u, myS, j);
                int s1 = __shfl_sync(~0u, myS, (j+1) & 31);
                int s2 = __shfl_sync(~0u, myS, (j+2) & 31);
                int s3 = __shfl_sync(~0u, myS, (j+3) & 31);
                float a0 = alt[(size_t)s0*Hh + hh];
                float a1 = alt[(size_t)s1*Hh + hh];
                float a2 = alt[(size_t)s2*Hh + hh];
                float a3 = alt[(size_t)s3*Hh + hh];
                float4 x0 = *(const float4*)(xwt + (size_t)s0*Dd + lane*4);
                float4 x1 = *(const float4*)(xwt + (size_t)s1*Dd + lane*4);
                float4 x2 = *(const float4*)(xwt + (size_t)s2*Dd + lane*4);
                float4 x3 = *(const float4*)(xwt + (size_t)s3*Dd + lane*4);
                float v0 = a0 + arn; v0 = v0 > 0.f ? v0 : NEG_SLOPE*v0;
                float v1 = a1 + arn; v1 = v1 > 0.f ? v1 : NEG_SLOPE*v1;
                float v2 = a2 + arn; v2 = v2 > 0.f ? v2 : NEG_SLOPE*v2;
                float v3 = a3 + arn; v3 = v3 > 0.f ? v3 : NEG_SLOPE*v3;
                float p0 = expf(v0);
                float p1 = (j+1 < cnt) ? expf(v1) : 0.f;
                float p2 = (j+2 < cnt) ? expf(v2) : 0.f;
                float p3 = (j+3 < cnt) ? expf(v3) : 0.f;
                s += p0 + p1 + p2 + p3;
                f.x += x0.x*p0 + x1.x*p1 + x2.x*p2 + x3.x*p3;
                f.y += x0.y*p0 + x1.y*p1 + x2.y*p2 + x3.y*p3;
                f.z += x0.z*p0 + x1.z*p1 + x2.z*p2 + x3.z*p3;
                f.w += x0.w*p0 + x1.w*p1 + x2.w*p2 + x3.w*p3;
            }
        }
        float inv = 1.f / s;
        *(float4*)(&smf[t][lane*4]) = make_float4(f.x*inv, f.y*inv, f.z*inv, f.w*inv);
    }
    __syncthreads();

    int d = tid;
    float a = smf[0][d] + smf[1][d] + smf[2][d] + smf[3][d]
            + b[d] + b[Dd + d] + b[2*Dd + d] + b[3*Dd + d];
    float ss = a*a;
    #pragma unroll
    for (int o = 16; o > 0; o >>= 1) ss += __shfl_xor_sync(0xffffffffu, ss, o);
    if (lane == 0) sw[t] = ss;
    __syncthreads();
    float tot = sw[0] + sw[1] + sw[2] + sw[3];
    float inv2 = rsqrtf(tot * (1.0f/Dd) + EPSF);
    int i = n*Dd + d;
    h[i] = geluf(h[i] + g[d] * a * inv2);
}

// ---------------- HGT gather: lane=(edge,head) attention pass — no shfl in chain
__global__ void hgt_gather_b(const int* __restrict__ csr, const int* __restrict__ off,
                             const int* __restrict__ deg, const float* __restrict__ k,
                             const float* __restrict__ q, const float* __restrict__ v,
                             const float* __restrict__ arel, const float* __restrict__ mrel,
                             const float* __restrict__ prel, float* __restrict__ out) {
    int n = blockIdx.x;
    int tid = threadIdx.x;
    int t = tid >> 5, lane = tid & 31;
    int hh = lane >> 2, qd = lane & 3;
    __shared__ float sq[128];
    __shared__ float sqa[4][128];
    __shared__ float smacc[4][128];
    __shared__ float sms[4][8];

    // stage this node's q row
    sq[tid] = q[(size_t)n*Dd + tid];
    __syncthreads();

    {
        // qA_i = sum_f arel[t][hh][qd*4+i][f] * q[hh*16+f]  -> smem (no shfl)
        const float* A = arel + ((size_t)(t*Hh + hh)*16 + qd*4)*16;
        const float* qs = &sq[hh*16];
        float qa0 = 0.f, qa1 = 0.f, qa2 = 0.f, qa3 = 0.f;
        #pragma unroll
        for (int f4 = 0; f4 < 4; f4++) {
            float4 qf = *(const float4*)(qs + f4*4);
            qa0 += dot4(*(const float4*)(A + 0*16 + f4*4), qf);
            qa1 += dot4(*(const float4*)(A + 1*16 + f4*4), qf);
            qa2 += dot4(*(const float4*)(A + 2*16 + f4*4), qf);
            qa3 += dot4(*(const float4*)(A + 3*16 + f4*4), qf);
        }
        *(float4*)(&sqa[t][lane*4]) = make_float4(qa0, qa1, qa2, qa3);
        __syncwarp();

        // attention lane mapping: eh = lane>>3 (edge in group of 4), ah = lane&7 (head)
        int eh = lane >> 3, ah = lane & 7;
        const float4* qa_h = (const float4*)(&sqa[t][ah*16]);
        float4 qh0 = qa_h[0], qh1 = qa_h[1], qh2 = qa_h[2], qh3 = qa_h[3];
        float pr_a = prel[t*Hh + ah] * 0.25f;   // my head's scale (attention pass)

        float4 aggv = make_float4(0,0,0,0);
        float s_l = 0.f;                         // per-lane partial softmax sum (head ah)
        int i0 = t*Nn + n, st = off[i0], dg = deg[i0];
        for (int j0 = 0; j0 < dg; j0 += 32) {
            int myS = (j0 + lane < dg) ? csr[st + j0 + lane] : 0;
            int cnt = min(32, dg - j0);
            for (int j = 0; j < cnt; j += 4) {
                // my edge for the attention pass:
                int je = j + eh;
                int srcA = __shfl_sync(~0u, myS, je & 31);
                // lane-local 16-wide dot: k[srcA][ah*16..+15] . qA[ah]
                const float4* kp = (const float4*)(k + (size_t)srcA*Dd + ah*16);
                float dt = dot4(kp[0], qh0) + dot4(kp[1], qh1)
                         + dot4(kp[2], qh2) + dot4(kp[3], qh3);
                float p_l = (je < cnt) ? expf(dt * pr_a) : 0.f;
                s_l += p_l;
                // v pass: broadcast p of edge e (head hh) from lane e*8+hh
                int s0 = __shfl_sync(~0u, myS, j);
                int s1 = __shfl_sync(~0u, myS, (j+1) & 31);
                int s2 = __shfl_sync(~0u, myS, (j+2) & 31);
                int s3 = __shfl_sync(~0u, myS, (j+3) & 31);
                float p0 = __shfl_sync(~0u, p_l, 0*8 + hh);
                float p1 = __shfl_sync(~0u, p_l, 1*8 + hh);
                float p2 = __shfl_sync(~0u, p_l, 2*8 + hh);
                float p3 = __shfl_sync(~0u, p_l, 3*8 + hh);
                float4 v0 = *(const float4*)(v + (size_t)s0*Dd + lane*4);
                float4 v1 = *(const float4*)(v + (size_t)s1*Dd + lane*4);
                float4 v2 = *(const float4*)(v + (size_t)s2*Dd + lane*4);
                float4 v3 = *(const float4*)(v + (size_t)s3*Dd + lane*4);
                aggv.x += v0.x*p0 + v1.x*p1 + v2.x*p2 + v3.x*p3;
                aggv.y += v0.y*p0 + v1.y*p1 + v2.y*p2 + v3.y*p3;
                aggv.z += v0.z*p0 + v1.z*p1 + v2.z*p2 + v3.z*p3;
                aggv.w += v0.w*p0 + v1.w*p1 + v2.w*p2 + v3.w*p3;
            }
        }
        // reduce per-head softmax sums across the 4 edge-groups (lanes +-8, +-16)
        s_l += __shfl_xor_sync(~0u, s_l, 8);
        s_l += __shfl_xor_sync(~0u, s_l, 16);
        *(float4*)(&smacc[t][lane*4]) = aggv;
        if (lane < 8) sms[t][lane] = s_l;
    }
    __syncthreads();

    // thread d: out[d] = gelu( (sum_t aggv_t @ mrel[t][dh]) [dq] / stot )
    int d = tid;
    int dh = d >> 4, dq = d & 15;
    float a = 0.f;
    #pragma unroll
    for (int t2 = 0; t2 < Tt; t2++) {
        const float* M = mrel + (size_t)((t2*Hh + dh)*16)*16;
        const float* av = &smacc[t2][dh*16];
        float sum = 0.f;
        #pragma unroll
        for (int j = 0; j < 16; j++)
            sum += av[j] * M[j*16 + dq];
        a += sum;
    }
    float stot = sms[0][dh] + sms[1][dh] + sms[2][dh] + sms[3][dh];
    float inv = 1.f / (stot > 0.f ? stot : 1.f);
    out[(size_t)n*Dd + d] = geluf(a * inv);
}

// ---------------- host launch ----------------
extern "C" void kernel_launch(void* const* d_in, const int* in_sizes, int n_in,
                              void* d_out, int out_size) {
    const float* zL  = (const float*)d_in[0];
    const float* zH  = (const float*)d_in[1];
    const float* xe  = (const float*)d_in[2];
    const float* W1  = (const float*)d_in[3];
    const float* as1 = (const float*)d_in[4];
    const float* ad1 = (const float*)d_in[5];
    const float* b1  = (const float*)d_in[6];
    const float* W2  = (const float*)d_in[7];
    const float* as2 = (const float*)d_in[8];
    const float* ad2 = (const float*)d_in[9];
    const float* b2  = (const float*)d_in[10];
    const float* Wk  = (const float*)d_in[11];
    const float* bk  = (const float*)d_in[12];
    const float* Wq  = (const float*)d_in[13];
    const float* bq  = (const float*)d_in[14];
    const float* Wv  = (const float*)d_in[15];
    const float* bv  = (const float*)d_in[16];
    const float* arel= (const float*)d_in[17];
    const float* mrel= (const float*)d_in[18];
    const float* prel= (const float*)d_in[19];
    const float* Wo  = (const float*)d_in[20];
    const float* bo  = (const float*)d_in[21];
    const float* skip= (const float*)d_in[22];
    const float* g1  = (const float*)d_in[23];
    const float* g2  = (const float*)d_in[24];
    const float* g3  = (const float*)d_in[25];
    const int* ei[4] = {(const int*)d_in[26], (const int*)d_in[27],
                        (const int*)d_in[28], (const int*)d_in[29]};

    float *h_, *k_, *q_, *v_, *tmp_, *al_, *ar_, *xw_;
    int *deg_, *off_, *cur_, *csr_, *bsum_;
    cudaGetSymbolAddress((void**)&h_,   g_h);
    cudaGetSymbolAddress((void**)&k_,   g_k);
    cudaGetSymbolAddress((void**)&q_,   g_q);
    cudaGetSymbolAddress((void**)&v_,   g_v);
    cudaGetSymbolAddress((void**)&tmp_, g_tmp);
    cudaGetSymbolAddress((void**)&al_,  g_al);
    cudaGetSymbolAddress((void**)&ar_,  g_ar);
    cudaGetSymbolAddress((void**)&xw_,  g_xw);
    cudaGetSymbolAddress((void**)&deg_, g_deg);
    cudaGetSymbolAddress((void**)&off_, g_off);
    cudaGetSymbolAddress((void**)&cur_, g_cur);
    cudaGetSymbolAddress((void**)&csr_, g_csr);
    cudaGetSymbolAddress((void**)&bsum_,g_bsum);

    const int TPB = 256;
    const int gemm_grid = (Nn + 127) / 128;

    zeroint<<<(TN + TPB-1)/TPB, TPB>>>(deg_, TN);                                   // 1
    deg_k<<<(E4 + TPB-1)/TPB, TPB>>>(ei[0], ei[1], ei[2], ei[3], deg_);             // 2
    scan_pre<<<SCAN_NB, 1024>>>(deg_, bsum_);                                       // 3
    // GAT layer 1 GEMM with fused add3 (writes h from t==0 blocks)
    gemm_ff<true><<<dim3(gemm_grid, Tt), TPB>>>(zL, zH, xe, h_, W1, xw_,
                                                as1, ad1, al_, ar_);                // 4 (profiled)
    scan_mid<<<1, 256>>>(bsum_);                                                    // 5
    scan_post<<<SCAN_NB, 1024>>>(deg_, bsum_, off_, cur_);                          // 6
    fill_k<<<(E4 + TPB-1)/TPB, TPB>>>(ei[0], ei[1], ei[2], ei[3], cur_, csr_);      // 7

    gat_gather_b<<<Nn, 128>>>(csr_, off_, deg_, al_, ar_, xw_, b1, g1, h_);         // 8

    // GAT layer 2
    gemm_ff<false><<<dim3(gemm_grid, Tt), TPB>>>(h_, nullptr, nullptr, nullptr,
                                                 W2, xw_, as2, ad2, al_, ar_);      // 9
    gat_gather_b<<<Nn, 128>>>(csr_, off_, deg_, al_, ar_, xw_, b2, g2, h_);         // 10

    // HGT
    gemm_kqv<<<dim3(gemm_grid, 3), TPB>>>(h_, Wk, bk, k_, Wq, bq, q_, Wv, bv, v_);  // 11
    hgt_gather_b<<<Nn, 128>>>(csr_, off_, deg_, k_, q_, v_, arel, mrel, prel, tmp_);// 12
    gemm_wo_post<<<gemm_grid, TPB>>>(tmp_, Wo, bo, h_, g3, skip, (float*)d_out);    // 13
}

// round 17
// speedup vs baseline: 1.0253x; 1.0253x over previous
#include <cuda_runtime.h>
#include <cuda_bf16.h>
#include <mma.h>
#include <math.h>
#include <stdint.h>

using namespace nvcuda;

#define Nn 50000
#define NP 50048                    /* Nn padded to 128 */
#define Dd 128
#define Tt 4
#define Ee 150000
#define Hh 8
#define E4  (Tt * Ee)
#define TN  (Tt * Nn)
#define NEG_SLOPE 0.2f
#define EPSF 1e-6f
#define SCAN_NB ((TN + 1023) / 1024)
#define WSEG 16384                  /* 128*128 */

// ---------------- scratch (static device globals; no allocation) ----------------
__device__ float g_h[Nn*Dd];
__device__ float g_k[Nn*Dd];
__device__ float g_q[Nn*Dd];
__device__ float g_v[Nn*Dd];
__device__ float g_tmp[Nn*Dd];
__device__ float g_al[TN*Hh];
__device__ float g_ar[TN*Hh];
__device__ float g_xw[(size_t)Tt*Nn*Dd];
__device__ __nv_bfloat16 g_hbf_hi[(size_t)NP*Dd];
__device__ __nv_bfloat16 g_hbf_lo[(size_t)NP*Dd];
__device__ __nv_bfloat16 g_wbf_hi[12*WSEG];
__device__ __nv_bfloat16 g_wbf_lo[12*WSEG];
__device__ int   g_deg[TN];
__device__ int   g_off[TN];
__device__ int   g_cur[TN];
__device__ int   g_csr[E4];
__device__ int   g_bsum[SCAN_NB];

// ---------------- generic helpers ----------------
__device__ __forceinline__ float geluf(float x) {
    return 0.5f * x * (1.0f + erff(x * 0.7071067811865476f));
}
__device__ __forceinline__ const int* pick_ei(int t, const int* e0, const int* e1,
                                              const int* e2, const int* e3) {
    return (t == 0) ? e0 : (t == 1) ? e1 : (t == 2) ? e2 : e3;
}
__device__ __forceinline__ float dot4(float4 a, float4 b) {
    return a.x*b.x + a.y*b.y + a.z*b.z + a.w*b.w;
}
__device__ __forceinline__ float4 shfl4(float4 v, int src) {
    float4 r;
    r.x = __shfl_sync(0xffffffffu, v.x, src);
    r.y = __shfl_sync(0xffffffffu, v.y, src);
    r.z = __shfl_sync(0xffffffffu, v.z, src);
    r.w = __shfl_sync(0xffffffffu, v.w, src);
    return r;
}
__device__ __forceinline__ unsigned pack2(float a, float b) {
    return ((unsigned)__bfloat16_as_ushort(__float2bfloat16(b)) << 16)
         | (unsigned)__bfloat16_as_ushort(__float2bfloat16(a));
}
__device__ __forceinline__ unsigned pack2res(float a, float b,
                                             unsigned hi) {
    float ah = __bfloat162float(__ushort_as_bfloat16((unsigned short)(hi & 0xffff)));
    float bh = __bfloat162float(__ushort_as_bfloat16((unsigned short)(hi >> 16)));
    return pack2(a - ah, b - bh);
}

// ---------------- elementwise / conversions ----------------
__global__ void add3k(const float4* __restrict__ a, const float4* __restrict__ b,
                      const float4* __restrict__ c, float4* __restrict__ o, int n4) {
    int i = blockIdx.x*blockDim.x + threadIdx.x;
    if (i < n4) {
        float4 x = a[i], y = b[i], z = c[i];
        o[i] = make_float4(x.x+y.x+z.x, x.y+y.y+z.y, x.z+y.z+z.z, x.w+y.w+z.w);
    }
}
__global__ void zeroint(int* __restrict__ p, int n) {
    int i = blockIdx.x*blockDim.x + threadIdx.x;
    if (i < n) p[i] = 0;
}
// split-bf16 convert: src fp32 [M x 128] -> hi/lo bf16 [NP x 128] (tail zeroed)
__global__ void cvt_h(const float* __restrict__ src, __nv_bfloat16* __restrict__ dh,
                      __nv_bfloat16* __restrict__ dl) {
    int g = blockIdx.x*blockDim.x + threadIdx.x;
    if (g >= NP*Dd/4) return;
    int base = g*4;
    float4 x = (base < Nn*Dd) ? *(const float4*)(src + base) : make_float4(0,0,0,0);
    unsigned h0 = pack2(x.x, x.y), h1 = pack2(x.z, x.w);
    unsigned l0 = pack2res(x.x, x.y, h0), l1 = pack2res(x.z, x.w, h1);
    ((uint2*)dh)[g] = make_uint2(h0, h1);
    ((uint2*)dl)[g] = make_uint2(l0, l1);
}
struct WPtrs { const float* w[12]; };
__global__ void cvt_w(WPtrs wp, __nv_bfloat16* __restrict__ dh,
                      __nv_bfloat16* __restrict__ dl) {
    int g = blockIdx.x*blockDim.x + threadIdx.x;
    if (g >= 12*WSEG/4) return;
    int base = g*4;
    int seg = base >> 14, off = base & (WSEG-1);
    float4 x = *(const float4*)(wp.w[seg] + off);
    unsigned h0 = pack2(x.x, x.y), h1 = pack2(x.z, x.w);
    unsigned l0 = pack2res(x.x, x.y, h0), l1 = pack2res(x.z, x.w, h1);
    ((uint2*)dh)[g] = make_uint2(h0, h1);
    ((uint2*)dl)[g] = make_uint2(l0, l1);
}

// ---------------- CSR build ----------------
__global__ void deg_k(const int* __restrict__ e0, const int* __restrict__ e1,
                      const int* __restrict__ e2, const int* __restrict__ e3,
                      int* __restrict__ deg) {
    int idx = blockIdx.x*blockDim.x + threadIdx.x;
    if (idx >= E4) return;
    int t = idx / Ee, e = idx - t*Ee;
    const int* ei = pick_ei(t, e0, e1, e2, e3);
    atomicAdd(&deg[t*Nn + ei[Ee + e]], 1);
}
__global__ void scan_pre(const int* __restrict__ deg, int* __restrict__ bsum) {
    __shared__ int sh[32];
    int g = blockIdx.x*1024 + threadIdx.x;
    int v = (g < TN) ? deg[g] : 0;
    int lane = threadIdx.x & 31, w = threadIdx.x >> 5;
    #pragma unroll
    for (int o = 16; o > 0; o >>= 1) v += __shfl_xor_sync(~0u, v, o);
    if (lane == 0) sh[w] = v;
    __syncthreads();
    if (w == 0) {
        int s = sh[lane];
        #pragma unroll
        for (int o = 16; o > 0; o >>= 1) s += __shfl_xor_sync(~0u, s, o);
        if (lane == 0) bsum[blockIdx.x] = s;
    }
}
__global__ void scan_mid(int* __restrict__ bsum) {
    __shared__ int ws[8];
    int tid = threadIdx.x;
    int v = (tid < SCAN_NB) ? bsum[tid] : 0;
    int lane = tid & 31, w = tid >> 5;
    int x = v;
    #pragma unroll
    for (int o = 1; o < 32; o <<= 1) { int u = __shfl_up_sync(~0u, x, o); if (lane >= o) x += u; }
    if (lane == 31) ws[w] = x;
    __syncthreads();
    if (w == 0 && lane < 8) {
        int y = ws[lane];
        #pragma unroll
        for (int o = 1; o < 8; o <<= 1) { int u = __shfl_up_sync(0xffu, y, o); if (lane >= o) y += u; }
        ws[lane] = y;
    }
    __syncthreads();
    int excl = x - v + (w > 0 ? ws[w-1] : 0);
    if (tid < SCAN_NB) bsum[tid] = excl;
}
__global__ void scan_post(const int* __restrict__ deg, const int* __restrict__ bsum,
                          int* __restrict__ off, int* __restrict__ cur) {
    __shared__ int ws[32];
    int g = blockIdx.x*1024 + threadIdx.x;
    int v = (g < TN) ? deg[g] : 0;
    int lane = threadIdx.x & 31, w = threadIdx.x >> 5;
    int x = v;
    #pragma unroll
    for (int o = 1; o < 32; o <<= 1) { int u = __shfl_up_sync(~0u, x, o); if (lane >= o) x += u; }
    if (lane == 31) ws[w] = x;
    __syncthreads();
    if (w == 0) {
        int y = ws[lane];
        #pragma unroll
        for (int o = 1; o < 32; o <<= 1) { int u = __shfl_up_sync(~0u, y, o); if (lane >= o) y += u; }
        ws[lane] = y;
    }
    __syncthreads();
    int excl = x - v + (w > 0 ? ws[w-1] : 0) + bsum[blockIdx.x];
    if (g < TN) { off[g] = excl; cur[g] = excl; }
}
__global__ void fill_k(const int* __restrict__ e0, const int* __restrict__ e1,
                       const int* __restrict__ e2, const int* __restrict__ e3,
                       int* __restrict__ cur, int* __restrict__ csr) {
    int idx = blockIdx.x*blockDim.x + threadIdx.x;
    if (idx >= E4) return;
    int t = idx / Ee, e = idx - t*Ee;
    const int* ei = pick_ei(t, e0, e1, e2, e3);
    int src = ei[e], dst = ei[Ee + e];
    int slot = atomicAdd(&cur[t*Nn + dst], 1);
    csr[slot] = src;
}

// ---------------- split-bf16 wmma GEMM (preconverted inputs) --------------------
// C[Nn x 128] = A @ W via A_hi*B_hi + A_lo*B_hi + A_hi*B_lo, fp32 accum.
// 128x128 block tile, 8 warps (each 32x64). A frags from GLOBAL bf16; B chunk
// staged in smem as plain copies. MODE 0: +bias (kqv). MODE 1: ALAR (GAT).
// MODE 2: Wo + HGT-post.
struct GemmArgs {
    const __nv_bfloat16 *ah, *alo;      // padded [NP x 128]
    const __nv_bfloat16 *wh, *wl;       // base of weight seg (t adds WSEG)
    const float* bias[4];
    float* C[4];
    const float* asb; const float* adb; float* alp; float* arp;  // MODE 1
    const float* hres; const float* g; const float* skip; float* out; // MODE 2
};

#define LDB 144
#define LDC 132

template <int MODE>
__global__ void __launch_bounds__(256, 2)
gemm_wm(GemmArgs a) {
    __shared__ __align__(16) unsigned char sm[32*LDC*4];   // 16896 B
    __nv_bfloat16 (*Bhi)[LDB] = (__nv_bfloat16 (*)[LDB])sm;
    __nv_bfloat16 (*Blo)[LDB] = (__nv_bfloat16 (*)[LDB])(sm + 16*LDB*2);
    float (*Cst)[LDC] = (float (*)[LDC])sm;                 // epilogue overlay

    const int t = blockIdx.y;
    const __nv_bfloat16* wh = a.wh + (size_t)t*WSEG;
    const __nv_bfloat16* wl = a.wl + (size_t)t*WSEG;
    const float* bias = a.bias[t];
    float* C = a.C[t];
    const int br = blockIdx.x * 128;
    const int tid = threadIdx.x;
    const int wid = tid >> 5;
    const int wm = wid & 3;        // 4 warp-rows of 32
    const int wn = wid >> 2;       // 2 warp-cols of 64

    wmma::fragment<wmma::accumulator, 16, 16, 16, float> acc[2][4];
    #pragma unroll
    for (int mi = 0; mi < 2; mi++)
        #pragma unroll
        for (int ni = 0; ni < 4; ni++) wmma::fill_fragment(acc[mi][ni], 0.0f);

    for (int kc = 0; kc < 8; kc++) {
        __syncthreads();
        {
            int row = tid >> 4, c8 = (tid & 15) * 8;
            *(uint4*)(&Bhi[row][c8]) =
                *(const uint4*)(wh + (size_t)(kc*16 + row)*Dd + c8);
            *(uint4*)(&Blo[row][c8]) =
                *(const uint4*)(wl + (size_t)(kc*16 + row)*Dd + c8);
        }
        __syncthreads();

        wmma::fragment<wmma::matrix_a, 16, 16, 16, __nv_bfloat16, wmma::row_major> afh[2], afl[2];
        #pragma unroll
        for (int mi = 0; mi < 2; mi++) {
            size_t rb = (size_t)(br + wm*32 + mi*16)*Dd + kc*16;
            wmma::load_matrix_sync(afh[mi], a.ah + rb, Dd);
            wmma::load_matrix_sync(afl[mi], a.alo + rb, Dd);
        }
        wmma::fragment<wmma::matrix_b, 16, 16, 16, __nv_bfloat16, wmma::row_major> bf[4];
        #pragma unroll
        for (int ni = 0; ni < 4; ni++)
            wmma::load_matrix_sync(bf[ni], &Bhi[0][wn*64 + ni*16], LDB);
        #pragma unroll
        for (int mi = 0; mi < 2; mi++)
            #pragma unroll
            for (int ni = 0; ni < 4; ni++) {
                wmma::mma_sync(acc[mi][ni], afh[mi], bf[ni], acc[mi][ni]);
                wmma::mma_sync(acc[mi][ni], afl[mi], bf[ni], acc[mi][ni]);
            }
        #pragma unroll
        for (int ni = 0; ni < 4; ni++)
            wmma::load_matrix_sync(bf[ni], &Blo[0][wn*64 + ni*16], LDB);
        #pragma unroll
        for (int mi = 0; mi < 2; mi++)
            #pragma unroll
            for (int ni = 0; ni < 4; ni++)
                wmma::mma_sync(acc[mi][ni], afh[mi], bf[ni], acc[mi][ni]);
    }

    // ---------------- epilogue: one 32-row warp-group at a time ----------------
    float beta = 0.f, omb = 0.f;
    if (MODE == 2) {
        beta = 1.f / (1.f + expf(-a.skip[0]));
        omb = 1.f - beta;
    }
    const int er = tid >> 3;            // 0..31 local row
    const int c0 = (tid & 7) * 16;      // one head's 16 cols
    const int head = tid & 7;

    for (int gstep = 0; gstep < 4; gstep++) {
        __syncthreads();
        if (wm == gstep) {
            #pragma unroll
            for (int mi = 0; mi < 2; mi++)
                #pragma unroll
                for (int ni = 0; ni < 4; ni++)
                    wmma::store_matrix_sync(&Cst[mi*16][wn*64 + ni*16], acc[mi][ni],
                                            LDC, wmma::mem_row_major);
        }
        __syncthreads();
        int gr = br + gstep*32 + er;
        bool valid = gr < Nn;
        float d[16];
        #pragma unroll
        for (int j = 0; j < 16; j++) d[j] = Cst[er][c0 + j];

        if (MODE == 0) {
            if (valid) {
                #pragma unroll
                for (int j4 = 0; j4 < 4; j4++) {
                    float4 o;
                    o.x = d[j4*4+0] + bias[c0 + j4*4+0];
                    o.y = d[j4*4+1] + bias[c0 + j4*4+1];
                    o.z = d[j4*4+2] + bias[c0 + j4*4+2];
                    o.w = d[j4*4+3] + bias[c0 + j4*4+3];
                    *(float4*)(C + (size_t)gr*Dd + c0 + j4*4) = o;
                }
            }
        } else if (MODE == 1) {
            if (valid) {
                float pa = 0.f, pr = 0.f;
                #pragma unroll
                for (int j = 0; j < 16; j++) {
                    pa += d[j] * a.asb[t*Dd + c0 + j];
                    pr += d[j] * a.adb[t*Dd + c0 + j];
                }
                #pragma unroll
                for (int j4 = 0; j4 < 4; j4++) {
                    float4 o;
                    o.x = d[j4*4+0]; o.y = d[j4*4+1]; o.z = d[j4*4+2]; o.w = d[j4*4+3];
                    *(float4*)(C + (size_t)gr*Dd + c0 + j4*4) = o;
                }
                int base = (t*Nn + gr)*Hh + head;
                a.alp[base] = pa;
                a.arp[base] = pr;
            }
        } else {
            float u[16], hv[16];
            float ss = 0.f;
            #pragma unroll
            for (int j = 0; j < 16; j++) {
                hv[j] = valid ? a.hres[(size_t)gr*Dd + c0 + j] : 0.f;
                u[j] = beta*(d[j] + bias[c0 + j]) + omb*hv[j];
                ss += u[j]*u[j];
            }
            ss += __shfl_xor_sync(~0u, ss, 1);
            ss += __shfl_xor_sync(~0u, ss, 2);
            ss += __shfl_xor_sync(~0u, ss, 4);
            float inv = rsqrtf(ss * (1.0f/Dd) + EPSF);
            if (valid) {
                #pragma unroll
                for (int j4 = 0; j4 < 4; j4++) {
                    float4 o;
                    #pragma unroll
                    for (int e = 0; e < 4; e++) {
                        int j = j4*4 + e;
                        float r = geluf(hv[j] + a.g[c0+j]*u[j]*inv);
                        if (e == 0) o.x = r; else if (e == 1) o.y = r;
                        else if (e == 2) o.z = r; else o.w = r;
                    }
                    *(float4*)(a.out + (size_t)gr*Dd + c0 + j4*4) = o;
                }
            }
        }
    }
}

// ---------------- GAT gather (round-14 version, unchanged) ----------------
__global__ void gat_gather_b(const int* __restrict__ csr, const int* __restrict__ off,
                             const int* __restrict__ deg, const float* __restrict__ al,
                             const float* __restrict__ ar, const float* __restrict__ xw,
                             const float* __restrict__ b, const float* __restrict__ g,
                             float* __restrict__ h) {
    int n = blockIdx.x;
    int tid = threadIdx.x;
    int t = tid >> 5, lane = tid & 31;
    int hh = lane >> 2;
    __shared__ float smf[4][128];
    __shared__ float sw[4];

    {
        int i = t*Nn + n;
        float arn = ar[(size_t)i*Hh + hh];
        float v = al[(size_t)i*Hh + hh] + arn;    // self loop
        v = v > 0.f ? v : NEG_SLOPE*v;
        float p = expf(v);
        float s = p;
        float4 x = *(const float4*)(xw + (size_t)i*Dd + lane*4);
        float4 f = make_float4(x.x*p, x.y*p, x.z*p, x.w*p);

        const float* alt = al + (size_t)t*Nn*Hh;
        const float* xwt = xw + (size_t)t*Nn*Dd;
        int st = off[i], dg = deg[i];
        for (int j0 = 0; j0 < dg; j0 += 32) {
            int myS = (j0 + lane < dg) ? csr[st + j0 + lane] : 0;
            int cnt = min(32, dg - j0);
            for (int j = 0; j < cnt; j += 4) {
                int s0 = __shfl_sync(~0u, myS, j);
                int s1 = __shfl_sync(~0u, myS, (j+1) & 31);
                int s2 = __shfl_sync(~0u, myS, (j+2) & 31);
                int s3 = __shfl_sync(~0u, myS, (j+3) & 31);
                float a0 = alt[(size_t)s0*Hh + hh];
                float a1 = alt[(size_t)s1*Hh + hh];
                float a2 = alt[(size_t)s2*Hh + hh];
                float a3 = alt[(size_t)s3*Hh + hh];
                float4 x0 = *(const float4*)(xwt + (size_t)s0*Dd + lane*4);
                float4 x1 = *(const float4*)(xwt + (size_t)s1*Dd + lane*4);
                float4 x2 = *(const float4*)(xwt + (size_t)s2*Dd + lane*4);
                float4 x3 = *(const float4*)(xwt + (size_t)s3*Dd + lane*4);
                float v0 = a0 + arn; v0 = v0 > 0.f ? v0 : NEG_SLOPE*v0;
                float v1 = a1 + arn; v1 = v1 > 0.f ? v1 : NEG_SLOPE*v1;
                float v2 = a2 + arn; v2 = v2 > 0.f ? v2 : NEG_SLOPE*v2;
                float v3 = a3 + arn; v3 = v3 > 0.f ? v3 : NEG_SLOPE*v3;
                float p0 = expf(v0);
                float p1 = (j+1 < cnt) ? expf(v1) : 0.f;
                float p2 = (j+2 < cnt) ? expf(v2) : 0.f;
                float p3 = (j+3 < cnt) ? expf(v3) : 0.f;
                s += p0 + p1 + p2 + p3;
                f.x += x0.x*p0 + x1.x*p1 + x2.x*p2 + x3.x*p3;
                f.y += x0.y*p0 + x1.y*p1 + x2.y*p2 + x3.y*p3;
                f.z += x0.z*p0 + x1.z*p1 + x2.z*p2 + x3.z*p3;
                f.w += x0.w*p0 + x1.w*p1 + x2.w*p2 + x3.w*p3;
            }
        }
        float inv = 1.f / s;
        *(float4*)(&smf[t][lane*4]) = make_float4(f.x*inv, f.y*inv, f.z*inv, f.w*inv);
    }
    __syncthreads();

    int d = tid;
    float a = smf[0][d] + smf[1][d] + smf[2][d] + smf[3][d]
            + b[d] + b[Dd + d] + b[2*Dd + d] + b[3*Dd + d];
    float ss = a*a;
    #pragma unroll
    for (int o = 16; o > 0; o >>= 1) ss += __shfl_xor_sync(0xffffffffu, ss, o);
    if (lane == 0) sw[t] = ss;
    __syncthreads();
    float tot = sw[0] + sw[1] + sw[2] + sw[3];
    float inv2 = rsqrtf(tot * (1.0f/Dd) + EPSF);
    int i = n*Dd + d;
    h[i] = geluf(h[i] + g[d] * a * inv2);
}

// ---------------- HGT gather (round-14 version, unchanged) ----------------
__global__ void hgt_gather_b(const int* __restrict__ csr, const int* __restrict__ off,
                             const int* __restrict__ deg, const float* __restrict__ k,
                             const float* __restrict__ q, const float* __restrict__ v,
                             const float* __restrict__ arel, const float* __restrict__ mrel,
                             const float* __restrict__ prel, float* __restrict__ out) {
    int n = blockIdx.x;
    int tid = threadIdx.x;
    int t = tid >> 5, lane = tid & 31;
    int hh = lane >> 2, qd = lane & 3;
    int qbase = lane & ~3;
    __shared__ float smacc[4][128];
    __shared__ float sms[4][8];

    {
        float4 qv = *(const float4*)(q + (size_t)n*Dd + lane*4);
        const float* A = arel + (size_t)((t*Hh + hh)*16)*16;
        float4 qA = make_float4(0,0,0,0);
        #pragma unroll
        for (int fq = 0; fq < 4; fq++) {
            float4 qb = shfl4(qv, qbase | fq);
            #pragma unroll
            for (int i = 0; i < 4; i++) {
                float4 a4 = *(const float4*)(A + (qd*4 + i)*16 + fq*4);
                float val = dot4(a4, qb);
                if (i == 0) qA.x += val;
                else if (i == 1) qA.y += val;
                else if (i == 2) qA.z += val;
                else qA.w += val;
            }
        }
        float pr = prel[t*Hh + hh] * 0.25f;

        float4 aggv = make_float4(0,0,0,0);
        float s = 0.f;
        int i0 = t*Nn + n, st = off[i0], dg = deg[i0];
        for (int j0 = 0; j0 < dg; j0 += 32) {
            int myS = (j0 + lane < dg) ? csr[st + j0 + lane] : 0;
            int cnt = min(32, dg - j0);
            for (int j = 0; j < cnt; j += 4) {
                int s0 = __shfl_sync(~0u, myS, j);
                int s1 = __shfl_sync(~0u, myS, (j+1) & 31);
                int s2 = __shfl_sync(~0u, myS, (j+2) & 31);
                int s3 = __shfl_sync(~0u, myS, (j+3) & 31);
                float4 k0 = *(const float4*)(k + (size_t)s0*Dd + lane*4);
                float4 k1 = *(const float4*)(k + (size_t)s1*Dd + lane*4);
                float4 k2 = *(const float4*)(k + (size_t)s2*Dd + lane*4);
                float4 k3 = *(const float4*)(k + (size_t)s3*Dd + lane*4);
                float4 v0 = *(const float4*)(v + (size_t)s0*Dd + lane*4);
                float4 v1 = *(const float4*)(v + (size_t)s1*Dd + lane*4);
                float4 v2 = *(const float4*)(v + (size_t)s2*Dd + lane*4);
                float4 v3 = *(const float4*)(v + (size_t)s3*Dd + lane*4);
                float pt0 = dot4(k0, qA);
                float pt1 = dot4(k1, qA);
                float pt2 = dot4(k2, qA);
                float pt3 = dot4(k3, qA);
                pt0 += __shfl_xor_sync(~0u, pt0, 1); pt0 += __shfl_xor_sync(~0u, pt0, 2);
                pt1 += __shfl_xor_sync(~0u, pt1, 1); pt1 += __shfl_xor_sync(~0u, pt1, 2);
                pt2 += __shfl_xor_sync(~0u, pt2, 1); pt2 += __shfl_xor_sync(~0u, pt2, 2);
                pt3 += __shfl_xor_sync(~0u, pt3, 1); pt3 += __shfl_xor_sync(~0u, pt3, 2);
                float p0 = expf(pt0 * pr);
                float p1 = (j+1 < cnt) ? expf(pt1 * pr) : 0.f;
                float p2 = (j+2 < cnt) ? expf(pt2 * pr) : 0.f;
                float p3 = (j+3 < cnt) ? expf(pt3 * pr) : 0.f;
                s += p0 + p1 + p2 + p3;
                aggv.x += v0.x*p0 + v1.x*p1 + v2.x*p2 + v3.x*p3;
                aggv.y += v0.y*p0 + v1.y*p1 + v2.y*p2 + v3.y*p3;
                aggv.z += v0.z*p0 + v1.z*p1 + v2.z*p2 + v3.z*p3;
                aggv.w += v0.w*p0 + v1.w*p1 + v2.w*p2 + v3.w*p3;
            }
        }
        const float* M = mrel + (size_t)((t*Hh + hh)*16)*16;
        float4 acc = make_float4(0,0,0,0);
        #pragma unroll
        for (int dq = 0; dq < 4; dq++) {
            float4 ab = shfl4(aggv, qbase | dq);
            float av[4] = {ab.x, ab.y, ab.z, ab.w};
            #pragma unroll
            for (int j = 0; j < 4; j++) {
                float4 m4 = *(const float4*)(M + (dq*4 + j)*16 + qd*4);
                float aj = av[j];
                acc.x += aj*m4.x; acc.y += aj*m4.y; acc.z += aj*m4.z; acc.w += aj*m4.w;
            }
        }
        *(float4*)(&smacc[t][lane*4]) = acc;
        if (qd == 0) sms[t][hh] = s;
    }
    __syncthreads();

    int d = tid;
    int dh = d >> 4;
    float a = smacc[0][d] + smacc[1][d] + smacc[2][d] + smacc[3][d];
    float stot = sms[0][dh] + sms[1][dh] + sms[2][dh] + sms[3][dh];
    float inv = 1.f / (stot > 0.f ? stot : 1.f);
    out[(size_t)n*Dd + d] = geluf(a * inv);
}

// ---------------- host launch ----------------
extern "C" void kernel_launch(void* const* d_in, const int* in_sizes, int n_in,
                              void* d_out, int out_size) {
    const float* zL  = (const float*)d_in[0];
    const float* zH  = (const float*)d_in[1];
    const float* xe  = (const float*)d_in[2];
    const float* W1  = (const float*)d_in[3];
    const float* as1 = (const float*)d_in[4];
    const float* ad1 = (const float*)d_in[5];
    const float* b1  = (const float*)d_in[6];
    const float* W2  = (const float*)d_in[7];
    const float* as2 = (const float*)d_in[8];
    const float* ad2 = (const float*)d_in[9];
    const float* b2  = (const float*)d_in[10];
    const float* Wk  = (const float*)d_in[11];
    const float* bk  = (const float*)d_in[12];
    const float* Wq  = (const float*)d_in[13];
    const float* bq  = (const float*)d_in[14];
    const float* Wv  = (const float*)d_in[15];
    const float* bv  = (const float*)d_in[16];
    const float* arel= (const float*)d_in[17];
    const float* mrel= (const float*)d_in[18];
    const float* prel= (const float*)d_in[19];
    const float* Wo  = (const float*)d_in[20];
    const float* bo  = (const float*)d_in[21];
    const float* skip= (const float*)d_in[22];
    const float* g1  = (const float*)d_in[23];
    const float* g2  = (const float*)d_in[24];
    const float* g3  = (const float*)d_in[25];
    const int* ei[4] = {(const int*)d_in[26], (const int*)d_in[27],
                        (const int*)d_in[28], (const int*)d_in[29]};

    float *h_, *k_, *q_, *v_, *tmp_, *al_, *ar_, *xw_;
    __nv_bfloat16 *hh_, *hl_, *wh_, *wl_;
    int *deg_, *off_, *cur_, *csr_, *bsum_;
    cudaGetSymbolAddress((void**)&h_,   g_h);
    cudaGetSymbolAddress((void**)&k_,   g_k);
    cudaGetSymbolAddress((void**)&q_,   g_q);
    cudaGetSymbolAddress((void**)&v_,   g_v);
    cudaGetSymbolAddress((void**)&tmp_, g_tmp);
    cudaGetSymbolAddress((void**)&al_,  g_al);
    cudaGetSymbolAddress((void**)&ar_,  g_ar);
    cudaGetSymbolAddress((void**)&xw_,  g_xw);
    cudaGetSymbolAddress((void**)&hh_,  g_hbf_hi);
    cudaGetSymbolAddress((void**)&hl_,  g_hbf_lo);
    cudaGetSymbolAddress((void**)&wh_,  g_wbf_hi);
    cudaGetSymbolAddress((void**)&wl_,  g_wbf_lo);
    cudaGetSymbolAddress((void**)&deg_, g_deg);
    cudaGetSymbolAddress((void**)&off_, g_off);
    cudaGetSymbolAddress((void**)&cur_, g_cur);
    cudaGetSymbolAddress((void**)&csr_, g_csr);
    cudaGetSymbolAddress((void**)&bsum_,g_bsum);

    const int nd = Nn*Dd;
    const int TPB = 256;
    const int gemm_grid = NP / 128;      // 391
    const int cvtg = (NP*Dd/4 + TPB-1)/TPB;

    WPtrs wp;
    for (int t = 0; t < 4; t++) { wp.w[t] = W1 + (size_t)t*WSEG; wp.w[4+t] = W2 + (size_t)t*WSEG; }
    wp.w[8] = Wk; wp.w[9] = Wq; wp.w[10] = Wv; wp.w[11] = Wo;

    // 1-3: h = zL+zH+xe; convert h and all weights to split-bf16
    add3k<<<(nd/4 + TPB-1)/TPB, TPB>>>((const float4*)zL, (const float4*)zH,
                                       (const float4*)xe, (float4*)h_, nd/4);       // 1
    cvt_h<<<cvtg, TPB>>>(h_, hh_, hl_);                                             // 2
    cvt_w<<<(12*WSEG/4 + TPB-1)/TPB, TPB>>>(wp, wh_, wl_);                          // 3

    GemmArgs ga = {};
    ga.ah = hh_; ga.alo = hl_;
    ga.asb = as1; ga.adb = ad1; ga.alp = al_; ga.arp = ar_;
    for (int t = 0; t < 4; t++) { ga.bias[t] = nullptr; ga.C[t] = xw_ + (size_t)t*Nn*Dd; }
    ga.wh = wh_; ga.wl = wl_;                  // W1 = segs 0..3
    gemm_wm<1><<<dim3(gemm_grid, Tt), TPB>>>(ga);                                   // 4 (profiled)

    // CSR build
    zeroint<<<(TN + TPB-1)/TPB, TPB>>>(deg_, TN);                                   // 5
    deg_k<<<(E4 + TPB-1)/TPB, TPB>>>(ei[0], ei[1], ei[2], ei[3], deg_);             // 6
    scan_pre<<<SCAN_NB, 1024>>>(deg_, bsum_);                                       // 7
    scan_mid<<<1, 256>>>(bsum_);                                                    // 8
    scan_post<<<SCAN_NB, 1024>>>(deg_, bsum_, off_, cur_);                          // 9
    fill_k<<<(E4 + TPB-1)/TPB, TPB>>>(ei[0], ei[1], ei[2], ei[3], cur_, csr_);      // 10

    gat_gather_b<<<Nn, 128>>>(csr_, off_, deg_, al_, ar_, xw_, b1, g1, h_);         // 11

    // GAT layer 2
    cvt_h<<<cvtg, TPB>>>(h_, hh_, hl_);                                             // 12
    ga.asb = as2; ga.adb = ad2;
    ga.wh = wh_ + 4*WSEG; ga.wl = wl_ + 4*WSEG;   // W2 = segs 4..7
    gemm_wm<1><<<dim3(gemm_grid, Tt), TPB>>>(ga);                                   // 13
    gat_gather_b<<<Nn, 128>>>(csr_, off_, deg_, al_, ar_, xw_, b2, g2, h_);         // 14

    // HGT: kqv
    cvt_h<<<cvtg, TPB>>>(h_, hh_, hl_);                                             // 15
    GemmArgs gk = {};
    gk.ah = hh_; gk.alo = hl_;
    gk.wh = wh_ + 8*WSEG; gk.wl = wl_ + 8*WSEG;   // Wk,Wq,Wv = segs 8..10
    gk.bias[0] = bk; gk.C[0] = k_;
    gk.bias[1] = bq; gk.C[1] = q_;
    gk.bias[2] = bv; gk.C[2] = v_;
    gemm_wm<0><<<dim3(gemm_grid, 3), TPB>>>(gk);                                    // 16
    hgt_gather_b<<<Nn, 128>>>(csr_, off_, deg_, k_, q_, v_, arel, mrel, prel, tmp_);// 17

    cvt_h<<<cvtg, TPB>>>(tmp_, hh_, hl_);                                           // 18
    GemmArgs gw = {};
    gw.ah = hh_; gw.alo = hl_;
    gw.wh = wh_ + 11*WSEG; gw.wl = wl_ + 11*WSEG; // Wo = seg 11
    gw.bias[0] = bo; gw.C[0] = nullptr;
    gw.hres = h_; gw.g = g3; gw.skip = skip; gw.out = (float*)d_out;
    gemm_wm<2><<<dim3(gemm_grid, 1), TPB>>>(gw);                                    // 19
}